// round 6
// baseline (speedup 1.0000x reference)
#include <cuda_runtime.h>
#include <cstdint>

#define BB 64
#define NN 500
#define CC 128
#define HH 256
#define GRIDN 128
#define THREADS 1024
#define XS_STRIDE 264   // 256 + 8 pad

// band thresholds squared (0.19^2, 0.21^2)
#define LO2 0.0361f
#define HI2 0.0441f

// MLP activation ping-pong + grid-barrier state
__device__ __align__(16) float g_act[2][BB * HH];
__device__ unsigned g_count[8];
__device__ volatile unsigned g_sense[8];

// Cooperative-groups-style grid barrier: fence ONLY in thread 0.
// __syncthreads() orders the whole CTA's global writes before thread 0 at CTA
// scope; thread 0's fence.gpu (cumulativity) publishes them GPU-wide before
// the signaling atomic. Waiter side: thread 0 fences after the spin; all
// cross-block data reads use __ldcg (L2-direct), so no stale-L1 hazard for
// the other threads.
__device__ __forceinline__ void grid_barrier(int idx)
{
    __syncthreads();
    if (threadIdx.x == 0) {
        __threadfence();                        // publish CTA writes
        unsigned s = g_sense[idx];
        unsigned arrived = atomicAdd(&g_count[idx], 1u);
        if (arrived == GRIDN - 1u) {
            g_count[idx] = 0u;
            __threadfence();
            g_sense[idx] = s + 1u;
        } else {
            while (g_sense[idx] == s) { }
        }
        __threadfence();                        // acquire side
    }
    __syncthreads();
}

// smem (dynamic, aliased between phases):
// Phase A: pj4 (512 float4, padded) | dataS 500*65 | corrS 64 | cnt
// Phase B: xs 64*264 | ws 2*264 | dotS 128 | mS 2 | iS 2
#define SMEM_FLOATS (4 * 512 + NN * 65 + 64 + 8)
#define SMEM_BYTES  (SMEM_FLOATS * 4)

__global__ __launch_bounds__(THREADS, 1)
void mega_kernel(const float* __restrict__ xyz,   // [B,3,N]
                 const float* __restrict__ pts,   // [B,C,N]
                 const float* __restrict__ l3,    // [B,C]
                 const float* __restrict__ temp,  // [B,1,N]
                 const float* __restrict__ w0, const float* __restrict__ b0,
                 const float* __restrict__ g0, const float* __restrict__ e0,
                 const float* __restrict__ w1, const float* __restrict__ b1,
                 const float* __restrict__ g1, const float* __restrict__ e1,
                 const float* __restrict__ w2, const float* __restrict__ b2,
                 const float* __restrict__ g2, const float* __restrict__ e2,
                 const float* __restrict__ w3, const float* __restrict__ b3,
                 const float* __restrict__ g3, const float* __restrict__ e3,
                 const float* __restrict__ w4, const float* __restrict__ b4,
                 float* __restrict__ tc,
                 float* __restrict__ tsys,
                 float* __restrict__ opts,
                 float* __restrict__ ocorr)
{
    extern __shared__ float sm[];
    const int tid  = threadIdx.x;
    const int bid  = blockIdx.x;
    const int warp = tid >> 5;
    const int lane = tid & 31;

    const int b    = bid >> 1;
    const int half = bid & 1;

    // ------------------------------------------------------------------
    // Phase A0: tsys (odd blocks)
    // ------------------------------------------------------------------
    if (half == 1) {
        float s = (tid < NN) ? temp[b * NN + tid] : 0.0f;
        #pragma unroll
        for (int off = 16; off; off >>= 1) s += __shfl_down_sync(0xffffffffu, s, off);
        if (lane == 0) sm[warp] = s;
        __syncthreads();
        if (tid < 32) {
            float v = (tid < 16) ? sm[tid] : 0.0f;
            #pragma unroll
            for (int off = 8; off; off >>= 1) v += __shfl_down_sync(0xffffffffu, v, off);
            if (tid == 0) tsys[b] = v * (1.0f / (float)NN);
        }
        __syncthreads();
    }

    // ------------------------------------------------------------------
    // Phase A1: l2_points passthrough copy (all blocks, float4)
    // ------------------------------------------------------------------
    {
        const float4* s4 = (const float4*)pts;
        float4*       d4 = (float4*)opts;
        const int total4 = (BB * CC * NN) / 4;
        #pragma unroll 2
        for (int i = bid * THREADS + tid; i < total4; i += GRIDN * THREADS)
            d4[i] = s4[i];
    }

    // ------------------------------------------------------------------
    // Phase A2: correlation. Upper-triangle (j > i) scan, squared band,
    // unified j-loop: pj4 padded to 512 with sentinels (pred false),
    // diagonal handled by post-ballot mask.
    // ------------------------------------------------------------------
    {
        float4* pj4   = (float4*)sm;           // 512 x {x,y,z,s}
        float*  dataS = sm + 4 * 512;          // NN * 65
        float*  corrS = dataS + NN * 65;       // 64
        int*    cntS  = (int*)(corrS + 64);

        if (tid < 64) corrS[tid] = 0.0f;
        if (tid == 64) *cntS = 0;

        const float* xb = xyz + (size_t)b * 3 * NN;
        if (tid < 512) {
            if (tid < NN) {
                float x = xb[tid];
                float y = xb[NN + tid];
                float z = xb[2 * NN + tid];
                pj4[tid] = make_float4(x, y, z, x * x + y * y + z * z);
            } else {
                pj4[tid] = make_float4(0.0f, 0.0f, 0.0f, 1.0e6f);  // sq ~ 1e6 -> pred false
            }
        }

        const float* pb = pts + (size_t)b * CC * NN + (size_t)half * 64 * NN;
        for (int idx = tid; idx < 64 * NN; idx += THREADS) {
            int c = idx / NN;
            int j = idx - c * NN;
            dataS[j * 65 + c] = pb[c * NN + j];
        }
        __syncthreads();

        float corr0 = 0.0f, corr1 = 0.0f;
        int   cnt   = 0;

        for (int i = warp; i < NN; i += 32) {
            const float4 pi = pj4[i];
            const float di0 = dataS[i * 65 + lane];
            const float di1 = dataS[i * 65 + 32 + lane];
            float t0 = 0.0f, t1 = 0.0f;

            const int jb0 = i & ~31;
            // first iteration: lanes 0..(i&31) are j<=i, invalid
            unsigned vmask = ~((2u << (i & 31)) - 1u);

            for (int jb = jb0; jb < NN; jb += 32) {
                float4 pj = pj4[jb + lane];
                float dot = pi.x * pj.x + pi.y * pj.y + pi.z * pj.z;
                float sq  = fabsf(pi.w + pj.w - 2.0f * dot);
                bool pred = (sq > LO2) && (sq < HI2);
                unsigned m = __ballot_sync(0xffffffffu, pred) & vmask;
                vmask = 0xffffffffu;
                cnt += __popc(m);
                while (m) {
                    int jj = jb + (__ffs(m) - 1);
                    m &= m - 1;
                    t0 += dataS[jj * 65 + lane];
                    t1 += dataS[jj * 65 + 32 + lane];
                }
            }

            corr0 += t0 * di0;
            corr1 += t1 * di1;
        }

        atomicAdd(&corrS[lane],      corr0);
        atomicAdd(&corrS[32 + lane], corr1);
        if (lane == 0) atomicAdd(cntS, cnt);
        __syncthreads();

        if (tid < 64) {
            float cf = fmaxf((float)(*cntS), 1.0f);
            ocorr[b * CC + half * 64 + tid] = corrS[tid] / cf;
        }
    }

    grid_barrier(0);

    // ------------------------------------------------------------------
    // Phase B: 4 BN-MLP layers. Each block owns 2 output columns.
    // ------------------------------------------------------------------
    {
        float* xs   = sm;                       // 64 * XS_STRIDE
        float* ws   = xs + BB * XS_STRIDE;      // 2 * XS_STRIDE
        float* dotS = ws + 2 * XS_STRIDE;       // 128
        float* mS   = dotS + 128;               // 2
        float* iS   = mS + 2;                   // 2

        const float* Wl[4] = {w0, w1, w2, w3};
        const float* Bl[4] = {b0, b1, b2, b3};
        const float* Gl[4] = {g0, g1, g2, g3};
        const float* El[4] = {e0, e1, e2, e3};

        const int o0 = bid * 2;

        for (int l = 0; l < 4; l++) {
            if (l == 0) {
                const float4* c4p = (const float4*)ocorr;
                const float4* l4p = (const float4*)l3;
                for (int i = tid; i < BB * 64; i += THREADS) {
                    int n = i >> 6, c4 = i & 63;
                    float4 v = (c4 < 32) ? __ldcg(c4p + n * 32 + c4)
                                         : __ldcg(l4p + n * 32 + (c4 - 32));
                    *(float4*)&xs[n * XS_STRIDE + c4 * 4] = v;
                }
            } else {
                const float4* src = (const float4*)&g_act[(l + 1) & 1][0];
                for (int i = tid; i < BB * 64; i += THREADS) {
                    int n = i >> 6, c4 = i & 63;
                    *(float4*)&xs[n * XS_STRIDE + c4 * 4] = __ldcg(src + i);
                }
            }
            if (tid < 2 * HH) {
                int oo = tid >> 8, k = tid & 255;
                ws[oo * XS_STRIDE + k] = Wl[l][(size_t)(o0 + oo) * HH + k];
            }
            __syncthreads();

            const int sub  = tid & 7;
            const int outi = tid >> 3;
            const int n    = outi >> 1;
            const int oc   = outi & 1;
            {
                const float* xr = &xs[n * XS_STRIDE + sub * 4];
                const float* wr = &ws[oc * XS_STRIDE + sub * 4];
                float p = 0.0f;
                #pragma unroll
                for (int t = 0; t < 8; t++) {
                    float4 xv = *(const float4*)(xr + t * 32);
                    float4 wv = *(const float4*)(wr + t * 32);
                    p = fmaf(xv.x, wv.x, p);
                    p = fmaf(xv.y, wv.y, p);
                    p = fmaf(xv.z, wv.z, p);
                    p = fmaf(xv.w, wv.w, p);
                }
                p += __shfl_down_sync(0xffffffffu, p, 4, 8);
                p += __shfl_down_sync(0xffffffffu, p, 2, 8);
                p += __shfl_down_sync(0xffffffffu, p, 1, 8);
                if (sub == 0) dotS[outi] = p + Bl[l][o0 + oc];
            }
            __syncthreads();

            if (tid < 64) {
                int oc2 = tid >> 5;
                int ll  = tid & 31;
                float a = dotS[ll * 2 + oc2];
                float c = dotS[(ll + 32) * 2 + oc2];
                float s = a + c, q = a * a + c * c;
                #pragma unroll
                for (int off = 16; off; off >>= 1) {
                    s += __shfl_down_sync(0xffffffffu, s, off);
                    q += __shfl_down_sync(0xffffffffu, q, off);
                }
                if (ll == 0) {
                    float m = s * (1.0f / 64.0f);
                    float v = q * (1.0f / 64.0f) - m * m;
                    mS[oc2] = m;
                    iS[oc2] = rsqrtf(v + 1e-5f);
                }
            }
            __syncthreads();

            if (tid < 128) {
                int nn = tid >> 1, occ = tid & 1;
                int o  = o0 + occ;
                float d = dotS[tid];
                float h = Gl[l][o] * (d - mS[occ]) * iS[occ] + El[l][o];
                g_act[l & 1][nn * HH + o] = fmaxf(h, 0.0f);
            }

            grid_barrier(1 + l);
        }
    }

    // ------------------------------------------------------------------
    // Final FC (block 0)
    // ------------------------------------------------------------------
    if (bid == 0) {
        const int n   = tid >> 4;
        const int sub = tid & 15;
        const float* hr = &g_act[1][n * HH + sub * 16];
        float p = 0.0f;
        #pragma unroll
        for (int t = 0; t < 16; t++)
            p = fmaf(__ldcg(hr + t), w4[sub * 16 + t], p);
        p += __shfl_down_sync(0xffffffffu, p, 8, 16);
        p += __shfl_down_sync(0xffffffffu, p, 4, 16);
        p += __shfl_down_sync(0xffffffffu, p, 2, 16);
        p += __shfl_down_sync(0xffffffffu, p, 1, 16);
        if (sub == 0) tc[n] = p + b4[0];
    }
}

// ---------------------------------------------------------------------------
extern "C" void kernel_launch(void* const* d_in, const int* in_sizes, int n_in,
                              void* d_out, int out_size)
{
    const float* xyz  = (const float*)d_in[0];
    const float* pts  = (const float*)d_in[1];
    const float* l3   = (const float*)d_in[2];
    const float* temp = (const float*)d_in[3];
    const float* w0   = (const float*)d_in[4];
    const float* b0   = (const float*)d_in[5];
    const float* g0   = (const float*)d_in[6];
    const float* e0   = (const float*)d_in[7];
    const float* w1   = (const float*)d_in[8];
    const float* b1   = (const float*)d_in[9];
    const float* g1   = (const float*)d_in[10];
    const float* e1   = (const float*)d_in[11];
    const float* w2   = (const float*)d_in[12];
    const float* b2   = (const float*)d_in[13];
    const float* g2   = (const float*)d_in[14];
    const float* e2   = (const float*)d_in[15];
    const float* w3   = (const float*)d_in[16];
    const float* b3   = (const float*)d_in[17];
    const float* g3   = (const float*)d_in[18];
    const float* e3   = (const float*)d_in[19];
    const float* w4   = (const float*)d_in[20];
    const float* b4   = (const float*)d_in[21];

    float* out   = (float*)d_out;
    float* tc    = out;
    float* tsys  = out + 64;
    float* opts  = out + 128;
    float* ocorr = out + 128 + (size_t)BB * CC * NN;

    cudaFuncSetAttribute(mega_kernel, cudaFuncAttributeMaxDynamicSharedMemorySize,
                         SMEM_BYTES);

    mega_kernel<<<GRIDN, THREADS, SMEM_BYTES>>>(
        xyz, pts, l3, temp,
        w0, b0, g0, e0,
        w1, b1, g1, e1,
        w2, b2, g2, e2,
        w3, b3, g3, e3,
        w4, b4,
        tc, tsys, opts, ocorr);

    (void)in_sizes; (void)n_in; (void)out_size;
}

// round 8
// speedup vs baseline: 1.5872x; 1.5872x over previous
#include <cuda_runtime.h>
#include <cstdint>

#define BB 64
#define NN 500
#define CC 128
#define HH 256
#define GRIDN 128
#define THREADS 1024
#define XS_STRIDE 264   // 256 + 8 pad

// band thresholds squared (0.19^2, 0.21^2)
#define LO2 0.0361f
#define HI2 0.0441f

// MLP activation ping-pong + grid-barrier state
__device__ __align__(16) float g_act[2][BB * HH];
__device__ unsigned g_count[8];
__device__ volatile unsigned g_sense[8];

// R5 barrier (measured fastest): all threads fence, thread 0 signals/spins.
__device__ __forceinline__ void grid_barrier(int idx)
{
    __threadfence();
    __syncthreads();
    if (threadIdx.x == 0) {
        unsigned s = g_sense[idx];
        unsigned arrived = atomicAdd(&g_count[idx], 1u);
        if (arrived == GRIDN - 1u) {
            g_count[idx] = 0u;
            __threadfence();
            g_sense[idx] = s + 1u;
        } else {
            while (g_sense[idx] == s) { }
        }
    }
    __syncthreads();
}

// smem (dynamic, aliased between phases):
// Phase A: pj4 (500 float4) | dataS 500*65 | corrS 64 | cnt
// Phase B: xs 64*264 | ws 2*264 | dotS 128 | mS 2 | iS 2
#define SMEM_FLOATS (4 * NN + NN * 65 + 64 + 8)
#define SMEM_BYTES  (SMEM_FLOATS * 4)

__global__ __launch_bounds__(THREADS, 1)
void mega_kernel(const float* __restrict__ xyz,   // [B,3,N]
                 const float* __restrict__ pts,   // [B,C,N]
                 const float* __restrict__ l3,    // [B,C]
                 const float* __restrict__ temp,  // [B,1,N]
                 const float* __restrict__ w0, const float* __restrict__ b0,
                 const float* __restrict__ g0, const float* __restrict__ e0,
                 const float* __restrict__ w1, const float* __restrict__ b1,
                 const float* __restrict__ g1, const float* __restrict__ e1,
                 const float* __restrict__ w2, const float* __restrict__ b2,
                 const float* __restrict__ g2, const float* __restrict__ e2,
                 const float* __restrict__ w3, const float* __restrict__ b3,
                 const float* __restrict__ g3, const float* __restrict__ e3,
                 const float* __restrict__ w4, const float* __restrict__ b4,
                 float* __restrict__ tc,
                 float* __restrict__ tsys,
                 float* __restrict__ opts,
                 float* __restrict__ ocorr)
{
    extern __shared__ float sm[];
    const int tid  = threadIdx.x;
    const int bid  = blockIdx.x;
    const int warp = tid >> 5;
    const int lane = tid & 31;

    const int b    = bid >> 1;
    const int half = bid & 1;

    // ------------------------------------------------------------------
    // Phase A0: tsys (odd blocks)
    // ------------------------------------------------------------------
    if (half == 1) {
        float s = (tid < NN) ? temp[b * NN + tid] : 0.0f;
        #pragma unroll
        for (int off = 16; off; off >>= 1) s += __shfl_down_sync(0xffffffffu, s, off);
        if (lane == 0) sm[warp] = s;
        __syncthreads();
        if (tid < 32) {
            float v = (tid < 16) ? sm[tid] : 0.0f;
            #pragma unroll
            for (int off = 8; off; off >>= 1) v += __shfl_down_sync(0xffffffffu, v, off);
            if (tid == 0) tsys[b] = v * (1.0f / (float)NN);
        }
        __syncthreads();
    }

    // ------------------------------------------------------------------
    // Phase A1: l2_points passthrough copy — streaming hints, no L1 pollution
    // ------------------------------------------------------------------
    {
        const float4* s4 = (const float4*)pts;
        float4*       d4 = (float4*)opts;
        const int total4 = (BB * CC * NN) / 4;
        #pragma unroll 2
        for (int i = bid * THREADS + tid; i < total4; i += GRIDN * THREADS)
            __stcs(d4 + i, __ldcs(s4 + i));
    }

    // ------------------------------------------------------------------
    // Phase A2: correlation. Upper-triangle scan (j > i), squared-band
    // predicate (no sqrt), float4-packed point records.  (R5 structure)
    // ------------------------------------------------------------------
    {
        float4* pj4   = (float4*)sm;           // 500 x {x,y,z,s}
        float*  dataS = sm + 4 * NN;           // NN * 65
        float*  corrS = dataS + NN * 65;       // 64
        int*    cntS  = (int*)(corrS + 64);

        if (tid < 64) corrS[tid] = 0.0f;
        if (tid == 64) *cntS = 0;

        const float* xb = xyz + (size_t)b * 3 * NN;
        for (int i = tid; i < NN; i += THREADS) {
            float x = xb[i];
            float y = xb[NN + i];
            float z = xb[2 * NN + i];
            pj4[i] = make_float4(x, y, z, x * x + y * y + z * z);
        }

        const float* pb = pts + (size_t)b * CC * NN + (size_t)half * 64 * NN;
        for (int idx = tid; idx < 64 * NN; idx += THREADS) {
            int c = idx / NN;
            int j = idx - c * NN;
            dataS[j * 65 + c] = pb[c * NN + j];
        }
        __syncthreads();

        float corr0 = 0.0f, corr1 = 0.0f;
        int   cnt   = 0;

        for (int i = warp; i < NN; i += 32) {
            const float4 pi = pj4[i];
            const float di0 = dataS[i * 65 + lane];
            const float di1 = dataS[i * 65 + 32 + lane];
            float t0 = 0.0f, t1 = 0.0f;

            const int jb0 = i & ~31;   // 32-aligned block containing i

            // diagonal block: j in [jb0, jb0+32), need j > i (and j < NN)
            {
                const int j = jb0 + lane;
                bool pred = false;
                if (j > i && j < NN) {
                    float4 pj = pj4[j];
                    float dot = pi.x * pj.x + pi.y * pj.y + pi.z * pj.z;
                    float sq  = fabsf(pi.w + pj.w - 2.0f * dot);
                    pred = (sq > LO2) && (sq < HI2);
                }
                unsigned m = __ballot_sync(0xffffffffu, pred);
                cnt += __popc(m);
                while (m) {
                    int jj = jb0 + (__ffs(m) - 1);
                    m &= m - 1;
                    t0 += dataS[jj * 65 + lane];
                    t1 += dataS[jj * 65 + 32 + lane];
                }
            }

            // full blocks: jb in (jb0, 480)
            #pragma unroll 2
            for (int jb = jb0 + 32; jb < 480; jb += 32) {
                float4 pj = pj4[jb + lane];
                float dot = pi.x * pj.x + pi.y * pj.y + pi.z * pj.z;
                float sq  = fabsf(pi.w + pj.w - 2.0f * dot);
                bool pred = (sq > LO2) && (sq < HI2);
                unsigned m = __ballot_sync(0xffffffffu, pred);
                cnt += __popc(m);
                while (m) {
                    int jj = jb + (__ffs(m) - 1);
                    m &= m - 1;
                    t0 += dataS[jj * 65 + lane];
                    t1 += dataS[jj * 65 + 32 + lane];
                }
            }

            // tail block jb=480 (j in [480,500)) when not already the diagonal
            if (jb0 < 480) {
                const int j = 480 + lane;
                bool pred = false;
                if (j < NN) {
                    float4 pj = pj4[j];
                    float dot = pi.x * pj.x + pi.y * pj.y + pi.z * pj.z;
                    float sq  = fabsf(pi.w + pj.w - 2.0f * dot);
                    pred = (sq > LO2) && (sq < HI2);
                }
                unsigned m = __ballot_sync(0xffffffffu, pred);
                cnt += __popc(m);
                while (m) {
                    int jj = 480 + (__ffs(m) - 1);
                    m &= m - 1;
                    t0 += dataS[jj * 65 + lane];
                    t1 += dataS[jj * 65 + 32 + lane];
                }
            }

            corr0 += t0 * di0;
            corr1 += t1 * di1;
        }

        atomicAdd(&corrS[lane],      corr0);
        atomicAdd(&corrS[32 + lane], corr1);
        if (lane == 0) atomicAdd(cntS, cnt);
        __syncthreads();

        if (tid < 64) {
            float cf = fmaxf((float)(*cntS), 1.0f);
            ocorr[b * CC + half * 64 + tid] = corrS[tid] / cf;
        }
    }

    grid_barrier(0);

    // ------------------------------------------------------------------
    // Phase B: 4 BN-MLP layers. Each block owns 2 output columns.
    // ------------------------------------------------------------------
    {
        float* xs   = sm;                       // 64 * XS_STRIDE
        float* ws   = xs + BB * XS_STRIDE;      // 2 * XS_STRIDE
        float* dotS = ws + 2 * XS_STRIDE;       // 128
        float* mS   = dotS + 128;               // 2
        float* iS   = mS + 2;                   // 2

        const float* Wl[4] = {w0, w1, w2, w3};
        const float* Bl[4] = {b0, b1, b2, b3};
        const float* Gl[4] = {g0, g1, g2, g3};
        const float* El[4] = {e0, e1, e2, e3};

        const int o0 = bid * 2;

        for (int l = 0; l < 4; l++) {
            if (l == 0) {
                const float4* c4p = (const float4*)ocorr;
                const float4* l4p = (const float4*)l3;
                for (int i = tid; i < BB * 64; i += THREADS) {
                    int n = i >> 6, c4 = i & 63;
                    float4 v = (c4 < 32) ? __ldcg(c4p + n * 32 + c4)
                                         : __ldcg(l4p + n * 32 + (c4 - 32));
                    *(float4*)&xs[n * XS_STRIDE + c4 * 4] = v;
                }
            } else {
                const float4* src = (const float4*)&g_act[(l + 1) & 1][0];
                for (int i = tid; i < BB * 64; i += THREADS) {
                    int n = i >> 6, c4 = i & 63;
                    *(float4*)&xs[n * XS_STRIDE + c4 * 4] = __ldcg(src + i);
                }
            }
            if (tid < 2 * HH) {
                int oo = tid >> 8, k = tid & 255;
                ws[oo * XS_STRIDE + k] = Wl[l][(size_t)(o0 + oo) * HH + k];
            }
            __syncthreads();

            const int sub  = tid & 7;
            const int outi = tid >> 3;
            const int n    = outi >> 1;
            const int oc   = outi & 1;
            {
                const float* xr = &xs[n * XS_STRIDE + sub * 4];
                const float* wr = &ws[oc * XS_STRIDE + sub * 4];
                float p = 0.0f;
                #pragma unroll
                for (int t = 0; t < 8; t++) {
                    float4 xv = *(const float4*)(xr + t * 32);
                    float4 wv = *(const float4*)(wr + t * 32);
                    p = fmaf(xv.x, wv.x, p);
                    p = fmaf(xv.y, wv.y, p);
                    p = fmaf(xv.z, wv.z, p);
                    p = fmaf(xv.w, wv.w, p);
                }
                p += __shfl_down_sync(0xffffffffu, p, 4, 8);
                p += __shfl_down_sync(0xffffffffu, p, 2, 8);
                p += __shfl_down_sync(0xffffffffu, p, 1, 8);
                if (sub == 0) dotS[outi] = p + Bl[l][o0 + oc];
            }
            __syncthreads();

            if (tid < 64) {
                int oc2 = tid >> 5;
                int ll  = tid & 31;
                float a = dotS[ll * 2 + oc2];
                float c = dotS[(ll + 32) * 2 + oc2];
                float s = a + c, q = a * a + c * c;
                #pragma unroll
                for (int off = 16; off; off >>= 1) {
                    s += __shfl_down_sync(0xffffffffu, s, off);
                    q += __shfl_down_sync(0xffffffffu, q, off);
                }
                if (ll == 0) {
                    float m = s * (1.0f / 64.0f);
                    float v = q * (1.0f / 64.0f) - m * m;
                    mS[oc2] = m;
                    iS[oc2] = rsqrtf(v + 1e-5f);
                }
            }
            __syncthreads();

            if (tid < 128) {
                int nn = tid >> 1, occ = tid & 1;
                int o  = o0 + occ;
                float d = dotS[tid];
                float h = Gl[l][o] * (d - mS[occ]) * iS[occ] + El[l][o];
                g_act[l & 1][nn * HH + o] = fmaxf(h, 0.0f);
            }

            grid_barrier(1 + l);
        }
    }

    // ------------------------------------------------------------------
    // Final FC (block 0)
    // ------------------------------------------------------------------
    if (bid == 0) {
        const int n   = tid >> 4;
        const int sub = tid & 15;
        const float* hr = &g_act[1][n * HH + sub * 16];
        float p = 0.0f;
        #pragma unroll
        for (int t = 0; t < 16; t++)
            p = fmaf(__ldcg(hr + t), w4[sub * 16 + t], p);
        p += __shfl_down_sync(0xffffffffu, p, 8, 16);
        p += __shfl_down_sync(0xffffffffu, p, 4, 16);
        p += __shfl_down_sync(0xffffffffu, p, 2, 16);
        p += __shfl_down_sync(0xffffffffu, p, 1, 16);
        if (sub == 0) tc[n] = p + b4[0];
    }
}

// ---------------------------------------------------------------------------
extern "C" void kernel_launch(void* const* d_in, const int* in_sizes, int n_in,
                              void* d_out, int out_size)
{
    const float* xyz  = (const float*)d_in[0];
    const float* pts  = (const float*)d_in[1];
    const float* l3   = (const float*)d_in[2];
    const float* temp = (const float*)d_in[3];
    const float* w0   = (const float*)d_in[4];
    const float* b0   = (const float*)d_in[5];
    const float* g0   = (const float*)d_in[6];
    const float* e0   = (const float*)d_in[7];
    const float* w1   = (const float*)d_in[8];
    const float* b1   = (const float*)d_in[9];
    const float* g1   = (const float*)d_in[10];
    const float* e1   = (const float*)d_in[11];
    const float* w2   = (const float*)d_in[12];
    const float* b2   = (const float*)d_in[13];
    const float* g2   = (const float*)d_in[14];
    const float* e2   = (const float*)d_in[15];
    const float* w3   = (const float*)d_in[16];
    const float* b3   = (const float*)d_in[17];
    const float* g3   = (const float*)d_in[18];
    const float* e3   = (const float*)d_in[19];
    const float* w4   = (const float*)d_in[20];
    const float* b4   = (const float*)d_in[21];

    float* out   = (float*)d_out;
    float* tc    = out;
    float* tsys  = out + 64;
    float* opts  = out + 128;
    float* ocorr = out + 128 + (size_t)BB * CC * NN;

    cudaFuncSetAttribute(mega_kernel, cudaFuncAttributeMaxDynamicSharedMemorySize,
                         SMEM_BYTES);

    mega_kernel<<<GRIDN, THREADS, SMEM_BYTES>>>(
        xyz, pts, l3, temp,
        w0, b0, g0, e0,
        w1, b1, g1, e1,
        w2, b2, g2, e2,
        w3, b3, g3, e3,
        w4, b4,
        tc, tsys, opts, ocorr);

    (void)in_sizes; (void)n_in; (void)out_size;
}